// round 17
// baseline (speedup 1.0000x reference)
#include <cuda_runtime.h>
#include <cuda_fp16.h>
#include <cstdint>

#define N_NODES 100000
#define D_IN    512
#define D_HID   256
#define D_OUT   32

// Scratch (device globals: no runtime allocation allowed)
__device__ float g_x[(size_t)N_NODES * D_OUT];    // 12.8 MB
// W1 in fragment-ordered fp16 layout: index ((kb*8 + nb)*4 + nt)*32 + lane
//   -> uint4 = k-pairs {lane&3, +4, +8, +12} of row n = nb*32 + nt*8 + (lane>>2)
__device__ uint4 g_w1f[16 * 8 * 4 * 32];          // 256 KB, L2-resident

// ---------------------------------------------------------------------------
__device__ __forceinline__ void mma_f16(
    float& d0, float& d1, float& d2, float& d3,
    uint32_t a0, uint32_t a1, uint32_t a2, uint32_t a3,
    uint32_t b0, uint32_t b1)
{
    asm volatile(
        "mma.sync.aligned.m16n8k16.row.col.f32.f16.f16.f32 "
        "{%0,%1,%2,%3},{%4,%5,%6,%7},{%8,%9},{%0,%1,%2,%3};"
        : "+f"(d0), "+f"(d1), "+f"(d2), "+f"(d3)
        : "r"(a0), "r"(a1), "r"(a2), "r"(a3), "r"(b0), "r"(b1));
}

__device__ __forceinline__ void red_v2(float* p, float v0, float v1) {
    asm volatile("red.global.add.v2.f32 [%0], {%1, %2};"
                 :: "l"(p), "f"(v0), "f"(v1) : "memory");
}

__device__ __forceinline__ void red_v4(float* p, float v0, float v1,
                                       float v2, float v3) {
    asm volatile("red.global.add.v4.f32 [%0], {%1, %2, %3, %4};"
                 :: "l"(p), "f"(v0), "f"(v1), "f"(v2), "f"(v3) : "memory");
}

__device__ __forceinline__ uint32_t h2bits(float lo, float hi) {
    __half2 h = __floats2half2_rn(lo, hi);
    return *reinterpret_cast<uint32_t*>(&h);
}

// ---------------------------------------------------------------------------
// Prep+Init fused:
//   range 0: out = 0                        (n4_out float4)
//   range 1: g_x[n][c] = b2[c]              (n4_x float4)
//   range 2: W1 -> g_w1f fragment layout    (65536 u32 elements)
// ---------------------------------------------------------------------------
__global__ void prep_init_kernel(float4* out, int n4_out,
                                 const float* __restrict__ b2,
                                 const float* __restrict__ W1)
{
    const int n4_x = N_NODES * (D_OUT / 4);
    int i = blockIdx.x * blockDim.x + threadIdx.x;
    if (i < n4_out) {
        out[i] = make_float4(0.f, 0.f, 0.f, 0.f);
    } else if (i < n4_out + n4_x) {
        int j = i - n4_out;
        int c = (j * 4) & (D_OUT - 1);
        float4 v;
        v.x = __ldg(b2 + c);     v.y = __ldg(b2 + c + 1);
        v.z = __ldg(b2 + c + 2); v.w = __ldg(b2 + c + 3);
        ((float4*)g_x)[j] = v;
    } else {
        int idx = i - n4_out - n4_x;            // u32 index into g_w1f
        if (idx < 16 * 8 * 4 * 32 * 4) {
            int e    = idx & 3;                 // u32 within uint4
            int lane = (idx >> 2) & 31;
            int nt   = (idx >> 7) & 3;
            int nb   = (idx >> 9) & 7;
            int kb   = idx >> 12;
            int n     = nb * 32 + nt * 8 + (lane >> 2);
            int kpair = (lane & 3) + 4 * e;
            int k     = kb * 32 + 2 * kpair;
            float w0 = W1[(size_t)k * D_HID + n];
            float w1 = W1[(size_t)(k + 1) * D_HID + n];
            ((uint32_t*)g_w1f)[idx] = h2bits(w0, w1);
        }
    }
}

// ---------------------------------------------------------------------------
// Fused GEMM (fp16): X += relu(F@W1+b1)[:, n0:n0+128] @ W2[n0:n0+128, :]
// CTA 128x128x32, 512 threads, 16 warps (4M x 4N), warp tile 32x32.
// A path identical to R10 (swizzled smem double buffer, conflict-free).
// B fragments loaded DIRECTLY from g_w1f (coalesced LDG.128, L2-resident):
// no B staging, no B smem, no B LDS.
// SMEM layout (u32): A0 @0  A1 @2048  w2p @4096  h2 @6144  h3 @8192
//                    total 10240 u32 = 40 KB static.
// Epilogue 1 h blocks: 0->A0, 1->A1, 2->h2, 3->h3.
// ---------------------------------------------------------------------------
#define G1_BK   32
#define G1_KIT  (D_IN / G1_BK)      // 16
#define LDH     16                  // u32 per smem row
#define HBUF    2048                // 128*16 u32 per buffer
#define OFF_W2P 4096
#define OFF_H23 6144
#define W2P_KB  512                 // 32*16 u32 per k-block

__device__ __forceinline__ uint32_t* hblk(uint32_t* smh, int b) {
    return (b < 2) ? (smh + b * HBUF) : (smh + OFF_H23 + (b - 2) * HBUF);
}

__global__ __launch_bounds__(512) void gemm_fused_kernel(
    const float* __restrict__ F,
    const float* __restrict__ b1,
    const float* __restrict__ W2)
{
    __shared__ uint32_t smh[10240];

    const int t    = threadIdx.x;
    const int lane = t & 31;
    const int wid  = t >> 5;           // 0..15
    const int wm   = wid & 3;          // warp M (0..3)
    const int wn   = wid >> 2;         // warp N (0..3)
    const int g    = lane >> 2;        // 0..7
    const int tig  = lane & 3;         // 0..3
    const int tigsw = ((tig ^ (g >> 1)) & 3) * 4;   // A fragment chunk offset

    const int n0 = blockIdx.x * 128;   // N fastest -> F L2 reuse (validated)
    const int m0 = blockIdx.y * 128;

    // ---- pre-permute W2 slice [n0:n0+128, 0:32] into w2p (fp16) ----
#pragma unroll
    for (int i = 0; i < 4; i++) {
        int idx   = t + i * 512;            // 0..2047
        int cpair = idx >> 5;               // h-col pair 0..63
        int np    = idx & 31;               // out col
        int c     = cpair * 2;
        float w0 = W2[(size_t)(n0 + c) * D_OUT + np];
        float w1 = W2[(size_t)(n0 + c + 1) * D_OUT + np];
        int kb    = cpair >> 4;             // k-block 0..3
        int cp    = cpair & 15;             // pair within block
        int chunk = (cp & 3) ^ ((np >> 1) & 3);
        int intra = cp >> 2;
        smh[OFF_W2P + kb * W2P_KB + np * LDH + chunk * 4 + intra] = h2bits(w0, w1);
    }

    // ---- A staging: row = t>>2, q = t&3 covers k [8q, 8q+8) ----
    const int srow = t >> 2;
    const int q    = t & 3;
    const int sws  = (srow >> 1) & 3;

    int arow = m0 + srow;
    if (arow >= N_NODES) arow = N_NODES - 1;   // clamp; outputs guarded
    const float* Ag = F + (size_t)arow * D_IN + q * 8;

    const int st0 = srow * LDH + ((0 ^ sws) * 4) + q;
    const int st1 = srow * LDH + ((1 ^ sws) * 4) + q;
    const int st2 = srow * LDH + ((2 ^ sws) * 4) + q;
    const int st3 = srow * LDH + ((3 ^ sws) * 4) + q;

    // B fragment gmem base for this warp: nb = blockIdx.x*4 + wn
    const uint4* Bf = g_w1f + (size_t)(blockIdx.x * 4 + wn) * 4 * 32 + lane;
    // per k-block stride: 8 nb * 4 nt * 32 lanes = 1024 uint4

    float4 va0, va1;
    va0 = *(const float4*)(Ag);
    va1 = *(const float4*)(Ag + 4);
    {
        uint32_t* As = smh;
        As[st0] = h2bits(va0.x, va0.y);
        As[st1] = h2bits(va0.z, va0.w);
        As[st2] = h2bits(va1.x, va1.y);
        As[st3] = h2bits(va1.z, va1.w);
    }
    __syncthreads();

    float acc[2][4][4];
#pragma unroll
    for (int i = 0; i < 2; i++)
#pragma unroll
        for (int j = 0; j < 4; j++)
#pragma unroll
            for (int c = 0; c < 4; c++) acc[i][j][c] = 0.f;

    const int am = wm * 32;

#pragma unroll 2
    for (int kb = 0; kb < G1_KIT; kb++) {
        if (kb + 1 < G1_KIT) {
            const float* pA = Ag + (kb + 1) * G1_BK;
            va0 = *(const float4*)(pA);
            va1 = *(const float4*)(pA + 4);
        }

        // B fragments straight from L2 (coalesced; issued first for overlap)
        uint4 bf[4];
        const uint4* Bkb = Bf + (size_t)kb * 1024;
#pragma unroll
        for (int nt = 0; nt < 4; nt++)
            bf[nt] = __ldg(Bkb + nt * 32);

        const uint32_t* As = smh + (kb & 1) * HBUF;
        uint4 alo[2], ahi[2];
#pragma unroll
        for (int mt = 0; mt < 2; mt++) {
            int r = am + mt * 16 + g;
            alo[mt] = *(const uint4*)(As + r * LDH + tigsw);
            ahi[mt] = *(const uint4*)(As + (r + 8) * LDH + tigsw);
        }
#pragma unroll
        for (int mt = 0; mt < 2; mt++) {
#pragma unroll
            for (int nt = 0; nt < 4; nt++) {
                // j = 0 (k 0..15): pairs tig, tig+4
                mma_f16(acc[mt][nt][0], acc[mt][nt][1],
                        acc[mt][nt][2], acc[mt][nt][3],
                        alo[mt].x, ahi[mt].x, alo[mt].y, ahi[mt].y,
                        bf[nt].x,  bf[nt].y);
                // j = 1 (k 16..31): pairs tig+8, tig+12
                mma_f16(acc[mt][nt][0], acc[mt][nt][1],
                        acc[mt][nt][2], acc[mt][nt][3],
                        alo[mt].z, ahi[mt].z, alo[mt].w, ahi[mt].w,
                        bf[nt].z,  bf[nt].w);
            }
        }

        if (kb + 1 < G1_KIT) {
            uint32_t* Aw = smh + ((kb + 1) & 1) * HBUF;
            Aw[st0] = h2bits(va0.x, va0.y);
            Aw[st1] = h2bits(va0.z, va0.w);
            Aw[st2] = h2bits(va1.x, va1.y);
            Aw[st3] = h2bits(va1.z, va1.w);
            __syncthreads();
        }
    }

    // ---- epilogue 1: bias + relu -> 4 h blocks (fp16, swizzled layout) ----
    __syncthreads();   // all fragment reads complete before overwrite
#pragma unroll
    for (int mt = 0; mt < 2; mt++) {
        const int lr = am + mt * 16 + g;
#pragma unroll
        for (int nt = 0; nt < 4; nt++) {
            const int cc0 = nt * 8 + 2 * tig;
            const int pos = tigsw + nt;          // 4*(tig^(g>>1)) + nt
            const float bx = __ldg(b1 + n0 + wn * 32 + cc0);
            const float by = __ldg(b1 + n0 + wn * 32 + cc0 + 1);
            uint32_t* hb = hblk(smh, wn);
            hb[lr * LDH + pos] =
                h2bits(fmaxf(acc[mt][nt][0] + bx, 0.f),
                       fmaxf(acc[mt][nt][1] + by, 0.f));
            hb[(lr + 8) * LDH + pos] =
                h2bits(fmaxf(acc[mt][nt][2] + bx, 0.f),
                       fmaxf(acc[mt][nt][3] + by, 0.f));
        }
    }
    __syncthreads();

    // ---- epilogue 2: X partial = h(128x128) @ W2p(128x32) via fp16 mma ----
    {
        const int wm2 = wid & 7;
        const int wn2 = wid >> 3;
        float xc[2][4];
#pragma unroll
        for (int nt = 0; nt < 2; nt++)
#pragma unroll
            for (int c = 0; c < 4; c++) xc[nt][c] = 0.f;

#pragma unroll
        for (int kb2 = 0; kb2 < 4; kb2++) {
            const uint32_t* Ah = hblk(smh, kb2);
            const uint32_t* Wp = smh + OFF_W2P + kb2 * W2P_KB;
            uint4 alo = *(const uint4*)(Ah + (wm2 * 16 + g) * LDH + tigsw);
            uint4 ahi = *(const uint4*)(Ah + (wm2 * 16 + 8 + g) * LDH + tigsw);
#pragma unroll
            for (int nt = 0; nt < 2; nt++) {
                uint4 bw = *(const uint4*)(Wp + (wn2 * 16 + nt * 8 + g) * LDH + tigsw);
                mma_f16(xc[nt][0], xc[nt][1], xc[nt][2], xc[nt][3],
                        alo.x, ahi.x, alo.y, ahi.y, bw.x, bw.y);
                mma_f16(xc[nt][0], xc[nt][1], xc[nt][2], xc[nt][3],
                        alo.z, ahi.z, alo.w, ahi.w, bw.z, bw.w);
            }
        }

        const int mrow = m0 + wm2 * 16 + g;
#pragma unroll
        for (int nt = 0; nt < 2; nt++) {
            const int np = wn2 * 16 + nt * 8 + 2 * tig;
            if (mrow < N_NODES)
                red_v2(g_x + (size_t)mrow * D_OUT + np, xc[nt][0], xc[nt][1]);
            if (mrow + 8 < N_NODES)
                red_v2(g_x + (size_t)(mrow + 8) * D_OUT + np, xc[nt][2], xc[nt][3]);
        }
    }
}

// ---------------------------------------------------------------------------
// Scatter: out[A_row[e], :] += A_data[e] * X[A_col[e], :]
// 8 threads/edge, one red.global.add.v4.f32 each (12.8M L2 atomic ops)
// ---------------------------------------------------------------------------
__global__ __launch_bounds__(256) void scatter_kernel(
    const float* __restrict__ A_data,
    const int*   __restrict__ A_row,
    const int*   __restrict__ A_col,
    float*       __restrict__ out,
    int n_edges)
{
    int idx = blockIdx.x * blockDim.x + threadIdx.x;
    int e = idx >> 3;
    int qq = idx & 7;
    if (e >= n_edges) return;

    float a = __ldg(A_data + e);
    int   r = __ldg(A_row + e);
    int   c = __ldg(A_col + e);

    float4 xv = *(const float4*)(g_x + (size_t)c * D_OUT + qq * 4);
    float* o  = out + (size_t)r * D_OUT + qq * 4;
    red_v4(o, a * xv.x, a * xv.y, a * xv.z, a * xv.w);
}

// ---------------------------------------------------------------------------
extern "C" void kernel_launch(void* const* d_in, const int* in_sizes, int n_in,
                              void* d_out, int out_size)
{
    const float* F      = (const float*)d_in[0];
    const float* A_data = (const float*)d_in[1];
    const float* W1     = (const float*)d_in[2];
    const float* b1     = (const float*)d_in[3];
    const float* W2     = (const float*)d_in[4];
    const float* b2     = (const float*)d_in[5];
    const int*   A_row  = (const int*)d_in[6];
    const int*   A_col  = (const int*)d_in[7];
    float* out = (float*)d_out;

    const int n_edges = in_sizes[1];

    // Fused prep (W1 -> fragment layout) + init (out = 0, g_x = b2)
    const int n4_out = out_size / 4;
    const int n4_x   = N_NODES * D_OUT / 4;
    const int n_w1f  = 16 * 8 * 4 * 32 * 4;   // u32 count = 65536
    const int tot_pi = n4_out + n4_x + n_w1f;
    prep_init_kernel<<<(tot_pi + 255) / 256, 256>>>((float4*)out, n4_out, b2, W1);

    // Fused GEMM (fp16 tensor cores; B fragments direct from L2)
    dim3 g1(D_HID / 128, (N_NODES + 127) / 128);
    gemm_fused_kernel<<<g1, 512>>>(F, b1, W2);

    // Scatter
    long long tot = (long long)n_edges * 8;
    int blocks = (int)((tot + 255) / 256);
    scatter_kernel<<<blocks, 256>>>(A_data, A_row, A_col, out, n_edges);
}